// round 10
// baseline (speedup 1.0000x reference)
#include <cuda_runtime.h>
#include <cuda_bf16.h>
#include <cstdint>
#include <cfloat>

#define K_CODES 1024
#define DIM     256
#define T_LEN   4096
#define B_SZ    16
#define N_ROWS  65536
#define QN      ((size_t)16777216)
#define RS      528                     // smem row stride (512B data + 16B pad)
#define TILE    (128 * RS)              // 67584 per tile
#define NTHR    512

__device__ __align__(256) __nv_bfloat16 g_A[(size_t)N_ROWS * DIM];    // 32 MB
__device__ __align__(256) __nv_bfloat16 g_Bm[(size_t)K_CODES * DIM];  // 512 KB
__device__ __align__(256) float g_enT[DIM * K_CODES];
__device__ float g_norm[N_ROWS];

__device__ __forceinline__ void cp16(uint32_t dst, const void* src) {
    asm volatile("cp.async.cg.shared.global [%0], [%1], 16;\n" :: "r"(dst), "l"(src));
}
__device__ __forceinline__ void cp_commit() { asm volatile("cp.async.commit_group;\n"); }
template <int N> __device__ __forceinline__ void cp_waitg() {
    asm volatile("cp.async.wait_group %0;\n" :: "n"(N));
}
__device__ __forceinline__ void ldsm4(uint32_t* r, uint32_t a) {
    asm volatile("ldmatrix.sync.aligned.m8n8.x4.shared.b16 {%0,%1,%2,%3}, [%4];"
                 : "=r"(r[0]), "=r"(r[1]), "=r"(r[2]), "=r"(r[3]) : "r"(a));
}
__device__ __forceinline__ void ldsm2(uint32_t* r, uint32_t a) {
    asm volatile("ldmatrix.sync.aligned.m8n8.x2.shared.b16 {%0,%1}, [%2];"
                 : "=r"(r[0]), "=r"(r[1]) : "r"(a));
}
__device__ __forceinline__ void mma16816(float* c, const uint32_t* a, const uint32_t* b) {
    asm volatile(
        "mma.sync.aligned.m16n8k16.row.col.f32.bf16.bf16.f32 "
        "{%0,%1,%2,%3},{%4,%5,%6,%7},{%8,%9},{%0,%1,%2,%3};"
        : "+f"(c[0]), "+f"(c[1]), "+f"(c[2]), "+f"(c[3])
        : "r"(a[0]), "r"(a[1]), "r"(a[2]), "r"(a[3]), "r"(b[0]), "r"(b[1]));
}

// --------- prep B: normalize embeddings -> g_enT (fp32) + g_Bm (bf16) ------
__global__ void vq_prepB(const float* __restrict__ emb,
                         float* __restrict__ out, long long out_size) {
    int k = blockIdx.x, d = threadIdx.x;
    float v = emb[(size_t)k * DIM + d];
    float s = v * v;
    #pragma unroll
    for (int o = 16; o; o >>= 1) s += __shfl_xor_sync(0xFFFFFFFFu, s, o);
    __shared__ float ws[8]; __shared__ float rs_sh;
    if ((d & 31) == 0) ws[d >> 5] = s;
    __syncthreads();
    if (d == 0) {
        float t = 0.f;
        #pragma unroll
        for (int i = 0; i < 8; i++) t += ws[i];
        rs_sh = 1.0f / fmaxf(sqrtf(t), 1e-12f);
        if (k == 0 && out_size > (long long)QN) out[QN] = 0.0f;
    }
    __syncthreads();
    float en = v * rs_sh;
    g_enT[(size_t)d * K_CODES + k] = en;
    g_Bm[(size_t)k * DIM + d] = __float2bfloat16(en);
}

// --------- prep A: transpose x -> g_A [n][d] bf16, norms --------------------
__global__ void vq_prepA(const float* __restrict__ x) {
    extern __shared__ float xs[];                 // [256][65]
    const int tid = threadIdx.x;
    const int b  = blockIdx.x >> 6;
    const int t0 = (blockIdx.x & 63) << 6;
    #pragma unroll
    for (int i = 0; i < 64; i++) {
        int lin = i * 256 + tid;
        int d = lin >> 6, tt = lin & 63;
        xs[d * 65 + tt] = x[((size_t)b * DIM + d) * T_LEN + t0 + tt];
    }
    __syncthreads();
    const int q = tid & 3, tt = tid >> 2;
    const int n = b * T_LEN + t0 + tt;
    __nv_bfloat16 hib[64];
    float ss = 0.f;
    #pragma unroll
    for (int dd = 0; dd < 64; dd++) {
        float v = xs[(q * 64 + dd) * 65 + tt];
        ss = fmaf(v, v, ss);
        hib[dd] = __float2bfloat16(v);
    }
    uint4* h4 = (uint4*)hib;
    uint4* d0 = (uint4*)(g_A + (size_t)n * DIM + q * 64);
    #pragma unroll
    for (int i = 0; i < 8; i++) d0[i] = h4[i];
    ss += __shfl_xor_sync(0xFFFFFFFFu, ss, 1);
    ss += __shfl_xor_sync(0xFFFFFFFFu, ss, 2);
    if (q == 0) g_norm[n] = sqrtf(ss);
}

// --------- main: bf16 mma.sync GEMM (A resident) + argmax + rescue ----------
__global__ void __launch_bounds__(NTHR, 1) vq_main_kernel(
    const float* __restrict__ x, const float* __restrict__ emb,
    float* __restrict__ out, long long out_size)
{
    extern __shared__ char smem[];
    const uint32_t sb = (uint32_t)__cvta_generic_to_shared(smem);
    const uint32_t sbB = sb + TILE;               // two B stages follow A
    const int tid  = threadIdx.x;
    const int lane = tid & 31;
    const int wid  = tid >> 5;
    const int wm   = wid & 3;            // 32-row group
    const int wn   = wid >> 2;           // 32-code group
    const int n0 = blockIdx.x * 128;
    const int b  = n0 >> 12;
    const int tl = n0 & 4095;

    // A tile: 128 rows x 256 bf16 (512B) -> smem rows of RS
    {
        const __nv_bfloat16* Asrc = g_A + (size_t)n0 * DIM;
        #pragma unroll
        for (int i = 0; i < 8; i++) {
            int lin = i * NTHR + tid;            // 0..4095
            int row = lin >> 5, q = lin & 31;
            cp16(sb + (uint32_t)(row * RS + q * 16), Asrc + (size_t)row * DIM + q * 8);
        }
        cp_commit();
    }
    auto loadB = [&](int nc) {
        const __nv_bfloat16* Bsrc = g_Bm + (size_t)(nc * 128) * DIM;
        uint32_t stg = sbB + (uint32_t)(nc & 1) * TILE;
        #pragma unroll
        for (int i = 0; i < 8; i++) {
            int lin = i * NTHR + tid;
            int row = lin >> 5, q = lin & 31;
            cp16(stg + (uint32_t)(row * RS + q * 16), Bsrc + (size_t)row * DIM + q * 8);
        }
        cp_commit();
    };
    loadB(0); loadB(1);

    float rm1[4], rm2[4];
    int   ri1[4];
    #pragma unroll
    for (int i = 0; i < 4; i++) { rm1[i] = -FLT_MAX; rm2[i] = -FLT_MAX; ri1[i] = 0; }

    #pragma unroll 1
    for (int nc = 0; nc < 8; nc++) {
        if (nc < 6) cp_waitg<1>(); else cp_waitg<0>();
        __syncthreads();                          // A + B-chunk nc resident

        float acc[2][4][4];
        #pragma unroll
        for (int mt = 0; mt < 2; mt++)
            #pragma unroll
            for (int nt = 0; nt < 4; nt++)
                #pragma unroll
                for (int c = 0; c < 4; c++) acc[mt][nt][c] = 0.f;

        const uint32_t stgB = sbB + (uint32_t)(nc & 1) * TILE;
        #pragma unroll 4
        for (int ks = 0; ks < 16; ks++) {
            uint32_t af[2][4], bf[4][2];
            #pragma unroll
            for (int mt = 0; mt < 2; mt++) {
                int row = wm * 32 + mt * 16 + (lane & 15);
                ldsm4(af[mt], sb + (uint32_t)(row * RS + ks * 32 + (lane >> 4) * 16));
            }
            #pragma unroll
            for (int nt = 0; nt < 4; nt++) {
                int rb = wn * 32 + nt * 8 + (lane & 7);
                ldsm2(bf[nt], stgB + (uint32_t)(rb * RS + ks * 32 + ((lane >> 3) & 1) * 16));
            }
            #pragma unroll
            for (int mt = 0; mt < 2; mt++)
                #pragma unroll
                for (int nt = 0; nt < 4; nt++)
                    mma16816(acc[mt][nt], af[mt], bf[nt]);
        }

        // fold this 128-code chunk into running top-2
        {
            int cb = nc * 128 + wn * 32 + 2 * (lane & 3);
            #pragma unroll
            for (int mt = 0; mt < 2; mt++)
                #pragma unroll
                for (int nt = 0; nt < 4; nt++) {
                    int col = cb + nt * 8;
                    #pragma unroll
                    for (int c = 0; c < 4; c++) {
                        int slot = mt * 2 + (c >> 1);
                        int ci = col + (c & 1);
                        float v = acc[mt][nt][c];
                        if (v > rm1[slot]) { rm2[slot] = rm1[slot]; rm1[slot] = v; ri1[slot] = ci; }
                        else if (v > rm2[slot]) rm2[slot] = v;
                    }
                }
        }
        __syncthreads();                          // stage nc&1 free
        if (nc + 2 < 8) loadB(nc + 2);
    }
    __syncthreads();

    // ---- cross-partition top-2 reduce (reuse A region as scratch) ----
    float* redm1 = (float*)smem;                 // [128][16]
    int*   redix = (int*)(smem + 8192);          // [128][16]
    float* redm2 = (float*)(smem + 16384);       // [128][16]
    const int p = wn * 4 + (lane & 3);
    #pragma unroll
    for (int slot = 0; slot < 4; slot++) {
        int row = wm * 32 + (slot >> 1) * 16 + (slot & 1) * 8 + (lane >> 2);
        redm1[row * 16 + p] = rm1[slot];
        redix[row * 16 + p] = ri1[slot];
        redm2[row * 16 + p] = rm2[slot];
    }
    __syncthreads();

    int*   idx_s = (int*)(smem + 24576);         // [128]
    int*   rlist = idx_s + 128;                  // [128]
    int*   rcnt  = idx_s + 256;
    float* xrow  = (float*)(idx_s + 260);        // [256]
    float* rv    = xrow + 256;                   // [512]
    int*   rix   = (int*)(rv + 512);             // [512]

    if (tid == 0) *rcnt = 0;
    __syncthreads();
    if (tid < 128) {
        float g1 = -FLT_MAX, g2 = -FLT_MAX; int gi = 0;
        #pragma unroll 1
        for (int j = 0; j < 16; j++) {
            float m1 = redm1[tid * 16 + j];
            float m2 = redm2[tid * 16 + j];
            int   ix = redix[tid * 16 + j];
            if (m1 > g1) { g2 = fmaxf(fmaxf(g1, m2), g2); g1 = m1; gi = ix; }
            else         { g2 = fmaxf(g2, m1); }
        }
        idx_s[tid] = gi;
        if (g1 - g2 < 2e-3f * g_norm[n0 + tid]) {   // 20-sigma of bf16 dot error
            int q = atomicAdd(rcnt, 1); rlist[q] = tid;
        }
    }
    __syncthreads();

    // ---- exact fp32 rescue for tight-margin rows ----
    const int nr = *rcnt;
    #pragma unroll 1
    for (int e = 0; e < nr; e++) {
        const int rr = rlist[e];
        const int tt = (n0 + rr) & 4095;
        if (tid < 256)
            xrow[tid] = x[((size_t)b * DIM + tid) * T_LEN + tt];
        __syncthreads();
        {
            int c = tid;
            float dot0 = 0.f, dot1 = 0.f;
            #pragma unroll 8
            for (int d = 0; d < 256; d++) {
                float xv = xrow[d];
                dot0 = fmaf(xv, g_enT[d * K_CODES + c], dot0);
                dot1 = fmaf(xv, g_enT[d * K_CODES + c + 512], dot1);
            }
            float bv; int bi;
            if (dot0 >= dot1) { bv = dot0; bi = c; } else { bv = dot1; bi = c + 512; }
            rv[tid] = bv; rix[tid] = bi;
        }
        __syncthreads();
        if (tid == 0) {
            float best = rv[0]; int besti = rix[0];
            #pragma unroll 1
            for (int j = 1; j < NTHR; j++) {
                float v = rv[j]; int ix = rix[j];
                if (v > best || (v == best && ix < besti)) { best = v; besti = ix; }
            }
            idx_s[rr] = besti;
        }
        __syncthreads();
    }

    if (tid < 128 && out_size >= (long long)(QN + 1 + N_ROWS))
        out[QN + 1 + n0 + tid] = (float)idx_s[tid];

    // ---- gather + quantized write + exact loss (512 threads: 64 dims each) --
    const int r  = tid & 127;
    const int dq = tid >> 7;
    const int myidx = idx_s[r];
    const float4* erow4 = (const float4*)(emb + (size_t)myidx * DIM + dq * 64);
    const float* xb = x + ((size_t)b * DIM + dq * 64) * T_LEN + tl + r;
    float* ob = out + ((size_t)b * DIM + dq * 64) * T_LEN + tl + r;
    float lsum = 0.f;
    #pragma unroll 4
    for (int dj = 0; dj < 16; ++dj) {
        float4 e4 = erow4[dj];
        int d = dj * 4;
        float ev[4] = {e4.x, e4.y, e4.z, e4.w};
        #pragma unroll
        for (int i = 0; i < 4; i++) {
            float xv = xb[(size_t)(d + i) * T_LEN];
            float df = ev[i] - xv;
            lsum = fmaf(df, df, lsum);
            ob[(size_t)(d + i) * T_LEN] = ev[i];
        }
    }
    #pragma unroll
    for (int o = 16; o; o >>= 1) lsum += __shfl_xor_sync(0xFFFFFFFFu, lsum, o);
    __shared__ float wsum[16];
    if ((tid & 31) == 0) wsum[wid] = lsum;
    __syncthreads();
    if (tid == 0) {
        float t = 0.f;
        #pragma unroll
        for (int i = 0; i < 16; i++) t += wsum[i];
        if (out_size > (long long)QN)
            atomicAdd(out + QN, t * (1.25f / 16777216.0f));
    }
}

// ---------------------------------------------------------------------------
extern "C" void kernel_launch(void* const* d_in, const int* in_sizes, int n_in,
                              void* d_out, int out_size) {
    const float* x   = (const float*)d_in[0];
    const float* emb = (const float*)d_in[1];
    if (n_in >= 2 && in_sizes[0] == K_CODES * DIM && in_sizes[1] == (int)QN) {
        const float* t = x; x = emb; emb = t;
    }
    float* out = (float*)d_out;

    const int smemA = 256 * 65 * 4;                  // 66560
    const int smemM = 3 * TILE;                      // 202752
    cudaFuncSetAttribute(vq_prepA, cudaFuncAttributeMaxDynamicSharedMemorySize, smemA);
    cudaFuncSetAttribute(vq_main_kernel, cudaFuncAttributeMaxDynamicSharedMemorySize, smemM);

    vq_prepB<<<K_CODES, 256>>>(emb, out, (long long)out_size);
    vq_prepA<<<B_SZ * 64, 256, smemA>>>(x);
    vq_main_kernel<<<N_ROWS / 128, NTHR, smemM>>>(x, emb, out, (long long)out_size);
}

// round 11
// speedup vs baseline: 4.0663x; 4.0663x over previous
#include <cuda_runtime.h>
#include <cuda_bf16.h>
#include <cstdint>
#include <cfloat>

#define K_CODES 1024
#define DIM     256
#define T_LEN   4096
#define B_SZ    16
#define N_ROWS  65536
#define QN      ((size_t)16777216)
#define RS      528                     // smem row stride (512B data + 16B pad)
#define TILE    (128 * RS)              // 67584 per tile
#define NTHR    512

__device__ __align__(256) __nv_bfloat16 g_A[(size_t)N_ROWS * DIM];    // 32 MB
__device__ __align__(256) __nv_bfloat16 g_Bm[(size_t)K_CODES * DIM];  // 512 KB
__device__ __align__(256) float g_enT[DIM * K_CODES];
__device__ float g_norm[N_ROWS];

__device__ __forceinline__ void cp16(uint32_t dst, const void* src) {
    asm volatile("cp.async.cg.shared.global [%0], [%1], 16;\n" :: "r"(dst), "l"(src));
}
__device__ __forceinline__ void cp_commit() { asm volatile("cp.async.commit_group;\n"); }
template <int N> __device__ __forceinline__ void cp_waitg() {
    asm volatile("cp.async.wait_group %0;\n" :: "n"(N));
}
__device__ __forceinline__ void ldsm4(uint32_t* r, uint32_t a) {
    asm volatile("ldmatrix.sync.aligned.m8n8.x4.shared.b16 {%0,%1,%2,%3}, [%4];"
                 : "=r"(r[0]), "=r"(r[1]), "=r"(r[2]), "=r"(r[3]) : "r"(a));
}
__device__ __forceinline__ void ldsm2(uint32_t* r, uint32_t a) {
    asm volatile("ldmatrix.sync.aligned.m8n8.x2.shared.b16 {%0,%1}, [%2];"
                 : "=r"(r[0]), "=r"(r[1]) : "r"(a));
}
__device__ __forceinline__ void mma16816(float* c, const uint32_t* a, const uint32_t* b) {
    asm volatile(
        "mma.sync.aligned.m16n8k16.row.col.f32.bf16.bf16.f32 "
        "{%0,%1,%2,%3},{%4,%5,%6,%7},{%8,%9},{%0,%1,%2,%3};"
        : "+f"(c[0]), "+f"(c[1]), "+f"(c[2]), "+f"(c[3])
        : "r"(a[0]), "r"(a[1]), "r"(a[2]), "r"(a[3]), "r"(b[0]), "r"(b[1]));
}

// --------- prep B: normalize embeddings -> g_enT (fp32) + g_Bm (bf16) ------
__global__ void vq_prepB(const float* __restrict__ emb,
                         float* __restrict__ out, long long out_size) {
    int k = blockIdx.x, d = threadIdx.x;
    float v = emb[(size_t)k * DIM + d];
    float s = v * v;
    #pragma unroll
    for (int o = 16; o; o >>= 1) s += __shfl_xor_sync(0xFFFFFFFFu, s, o);
    __shared__ float ws[8]; __shared__ float rs_sh;
    if ((d & 31) == 0) ws[d >> 5] = s;
    __syncthreads();
    if (d == 0) {
        float t = 0.f;
        #pragma unroll
        for (int i = 0; i < 8; i++) t += ws[i];
        rs_sh = 1.0f / fmaxf(sqrtf(t), 1e-12f);
        if (k == 0 && out_size > (long long)QN) out[QN] = 0.0f;
    }
    __syncthreads();
    float en = v * rs_sh;
    g_enT[(size_t)d * K_CODES + k] = en;
    g_Bm[(size_t)k * DIM + d] = __float2bfloat16(en);
}

// --------- prep A: transpose x -> g_A [n][d] bf16, norms --------------------
__global__ void vq_prepA(const float* __restrict__ x) {
    extern __shared__ float xs[];                 // [256][65]
    const int tid = threadIdx.x;
    const int b  = blockIdx.x >> 6;
    const int t0 = (blockIdx.x & 63) << 6;
    #pragma unroll
    for (int i = 0; i < 64; i++) {
        int lin = i * 256 + tid;
        int d = lin >> 6, tt = lin & 63;
        xs[d * 65 + tt] = x[((size_t)b * DIM + d) * T_LEN + t0 + tt];
    }
    __syncthreads();
    const int q = tid & 3, tt = tid >> 2;
    const int n = b * T_LEN + t0 + tt;
    __nv_bfloat16 hib[64];
    float ss = 0.f;
    #pragma unroll
    for (int dd = 0; dd < 64; dd++) {
        float v = xs[(q * 64 + dd) * 65 + tt];
        ss = fmaf(v, v, ss);
        hib[dd] = __float2bfloat16(v);
    }
    uint4* h4 = (uint4*)hib;
    uint4* d0 = (uint4*)(g_A + (size_t)n * DIM + q * 64);
    #pragma unroll
    for (int i = 0; i < 8; i++) d0[i] = h4[i];
    ss += __shfl_xor_sync(0xFFFFFFFFu, ss, 1);
    ss += __shfl_xor_sync(0xFFFFFFFFu, ss, 2);
    if (q == 0) g_norm[n] = sqrtf(ss);
}

// --------- main: bf16 mma.sync GEMM (A resident) + argmax + batched rescue --
__global__ void __launch_bounds__(NTHR, 1) vq_main_kernel(
    const float* __restrict__ x, const float* __restrict__ emb,
    float* __restrict__ out, long long out_size)
{
    extern __shared__ char smem[];
    const uint32_t sb = (uint32_t)__cvta_generic_to_shared(smem);
    const uint32_t sbB = sb + TILE;               // two B stages follow A
    const int tid  = threadIdx.x;
    const int lane = tid & 31;
    const int wid  = tid >> 5;
    const int wm   = wid & 3;            // 32-row group
    const int wn   = wid >> 2;           // 32-code group
    const int n0 = blockIdx.x * 128;
    const int b  = n0 >> 12;
    const int tl = n0 & 4095;

    // A tile: 128 rows x 256 bf16 (512B) -> smem rows of RS
    {
        const __nv_bfloat16* Asrc = g_A + (size_t)n0 * DIM;
        #pragma unroll
        for (int i = 0; i < 8; i++) {
            int lin = i * NTHR + tid;            // 0..4095
            int row = lin >> 5, q = lin & 31;
            cp16(sb + (uint32_t)(row * RS + q * 16), Asrc + (size_t)row * DIM + q * 8);
        }
        cp_commit();
    }
    auto loadB = [&](int nc) {
        const __nv_bfloat16* Bsrc = g_Bm + (size_t)(nc * 128) * DIM;
        uint32_t stg = sbB + (uint32_t)(nc & 1) * TILE;
        #pragma unroll
        for (int i = 0; i < 8; i++) {
            int lin = i * NTHR + tid;
            int row = lin >> 5, q = lin & 31;
            cp16(stg + (uint32_t)(row * RS + q * 16), Bsrc + (size_t)row * DIM + q * 8);
        }
        cp_commit();
    };
    loadB(0); loadB(1);

    float rm1[4], rm2[4];
    int   ri1[4];
    #pragma unroll
    for (int i = 0; i < 4; i++) { rm1[i] = -FLT_MAX; rm2[i] = -FLT_MAX; ri1[i] = 0; }

    #pragma unroll 1
    for (int nc = 0; nc < 8; nc++) {
        if (nc < 6) cp_waitg<1>(); else cp_waitg<0>();
        __syncthreads();                          // A + B-chunk nc resident

        float acc[2][4][4];
        #pragma unroll
        for (int mt = 0; mt < 2; mt++)
            #pragma unroll
            for (int nt = 0; nt < 4; nt++)
                #pragma unroll
                for (int c = 0; c < 4; c++) acc[mt][nt][c] = 0.f;

        const uint32_t stgB = sbB + (uint32_t)(nc & 1) * TILE;
        #pragma unroll 4
        for (int ks = 0; ks < 16; ks++) {
            uint32_t af[2][4], bf[4][2];
            #pragma unroll
            for (int mt = 0; mt < 2; mt++) {
                int row = wm * 32 + mt * 16 + (lane & 15);
                ldsm4(af[mt], sb + (uint32_t)(row * RS + ks * 32 + (lane >> 4) * 16));
            }
            #pragma unroll
            for (int nt = 0; nt < 4; nt++) {
                int rb = wn * 32 + nt * 8 + (lane & 7);
                ldsm2(bf[nt], stgB + (uint32_t)(rb * RS + ks * 32 + ((lane >> 3) & 1) * 16));
            }
            #pragma unroll
            for (int mt = 0; mt < 2; mt++)
                #pragma unroll
                for (int nt = 0; nt < 4; nt++)
                    mma16816(acc[mt][nt], af[mt], bf[nt]);
        }

        // fold this 128-code chunk into running top-2
        {
            int cb = nc * 128 + wn * 32 + 2 * (lane & 3);
            #pragma unroll
            for (int mt = 0; mt < 2; mt++)
                #pragma unroll
                for (int nt = 0; nt < 4; nt++) {
                    int col = cb + nt * 8;
                    #pragma unroll
                    for (int c = 0; c < 4; c++) {
                        int slot = mt * 2 + (c >> 1);
                        int ci = col + (c & 1);
                        float v = acc[mt][nt][c];
                        if (v > rm1[slot]) { rm2[slot] = rm1[slot]; rm1[slot] = v; ri1[slot] = ci; }
                        else if (v > rm2[slot]) rm2[slot] = v;
                    }
                }
        }
        __syncthreads();                          // stage nc&1 free
        if (nc + 2 < 8) loadB(nc + 2);
    }
    __syncthreads();

    // ---- cross-partition top-2 reduce (reuse A region as scratch) ----
    float* redm1 = (float*)smem;                 // [128][16]
    int*   redix = (int*)(smem + 8192);          // [128][16]
    float* redm2 = (float*)(smem + 16384);       // [128][16]
    const int p = wn * 4 + (lane & 3);
    #pragma unroll
    for (int slot = 0; slot < 4; slot++) {
        int row = wm * 32 + (slot >> 1) * 16 + (slot & 1) * 8 + (lane >> 2);
        redm1[row * 16 + p] = rm1[slot];
        redix[row * 16 + p] = ri1[slot];
        redm2[row * 16 + p] = rm2[slot];
    }
    __syncthreads();

    int*   idx_s = (int*)(smem + 24576);         // [128]
    int*   rlist = idx_s + 128;                  // [128]
    int*   rcnt  = idx_s + 256;
    float* xs8   = (float*)(smem + 28672);       // [8][256] = 8KB
    float* rwv   = (float*)(smem + 36864);       // [8][16]
    int*   rwi   = (int*)(smem + 37376);         // [8][16]

    if (tid == 0) *rcnt = 0;
    __syncthreads();
    if (tid < 128) {
        float g1 = -FLT_MAX, g2 = -FLT_MAX; int gi = 0;
        #pragma unroll 1
        for (int j = 0; j < 16; j++) {
            float m1 = redm1[tid * 16 + j];
            float m2 = redm2[tid * 16 + j];
            int   ix = redix[tid * 16 + j];
            if (m1 > g1) { g2 = fmaxf(fmaxf(g1, m2), g2); g1 = m1; gi = ix; }
            else         { g2 = fmaxf(g2, m1); }
        }
        idx_s[tid] = gi;
        if (g1 - g2 < 1e-3f * g_norm[n0 + tid]) {   // ~7 sigma of bf16 dot-diff error
            int q = atomicAdd(rcnt, 1); rlist[q] = tid;
        }
    }
    __syncthreads();

    // ---- batched exact fp32 rescue: 8 rows per g_enT sweep ----
    const int nr = *rcnt;
    #pragma unroll 1
    for (int e0 = 0; e0 < nr; e0 += 8) {
        const int nb = min(8, nr - e0);
        // load up to 8 x-rows (fp32) into smem
        #pragma unroll
        for (int i = 0; i < 4; i++) {
            int lin = i * NTHR + tid;            // 0..2047
            int r = lin >> 8, d = lin & 255;
            int rr = rlist[e0 + (r < nb ? r : 0)];
            xs8[r * 256 + d] = x[((size_t)b * DIM + d) * T_LEN + ((n0 + rr) & 4095)];
        }
        __syncthreads();
        float a0[8], a1[8];
        #pragma unroll
        for (int r = 0; r < 8; r++) { a0[r] = 0.f; a1[r] = 0.f; }
        #pragma unroll 4
        for (int d = 0; d < 256; d++) {
            float e0v = g_enT[d * K_CODES + tid];          // coalesced
            float e1v = g_enT[d * K_CODES + tid + 512];
            #pragma unroll
            for (int r = 0; r < 8; r++) {
                float xv = xs8[r * 256 + d];               // broadcast
                a0[r] = fmaf(xv, e0v, a0[r]);
                a1[r] = fmaf(xv, e1v, a1[r]);
            }
        }
        #pragma unroll 1
        for (int r = 0; r < nb; r++) {
            float bv = a0[r]; int bi = tid;
            if (a1[r] > bv) { bv = a1[r]; bi = tid + 512; }
            #pragma unroll
            for (int o = 16; o; o >>= 1) {
                float ov = __shfl_xor_sync(0xFFFFFFFFu, bv, o);
                int   oi = __shfl_xor_sync(0xFFFFFFFFu, bi, o);
                if (ov > bv || (ov == bv && oi < bi)) { bv = ov; bi = oi; }
            }
            if (lane == 0) { rwv[r * 16 + wid] = bv; rwi[r * 16 + wid] = bi; }
        }
        __syncthreads();
        if (tid < nb) {
            float best = rwv[tid * 16]; int besti = rwi[tid * 16];
            #pragma unroll
            for (int j = 1; j < 16; j++) {
                float v = rwv[tid * 16 + j]; int ix = rwi[tid * 16 + j];
                if (v > best || (v == best && ix < besti)) { best = v; besti = ix; }
            }
            idx_s[rlist[e0 + tid]] = besti;
        }
        __syncthreads();
    }

    if (tid < 128 && out_size >= (long long)(QN + 1 + N_ROWS))
        out[QN + 1 + n0 + tid] = (float)idx_s[tid];

    // ---- gather + quantized write + exact loss (512 threads: 64 dims each) --
    const int r  = tid & 127;
    const int dq = tid >> 7;
    const int myidx = idx_s[r];
    const float4* erow4 = (const float4*)(emb + (size_t)myidx * DIM + dq * 64);
    const float* xb = x + ((size_t)b * DIM + dq * 64) * T_LEN + tl + r;
    float* ob = out + ((size_t)b * DIM + dq * 64) * T_LEN + tl + r;
    float lsum = 0.f;
    #pragma unroll 4
    for (int dj = 0; dj < 16; ++dj) {
        float4 e4 = erow4[dj];
        int d = dj * 4;
        float ev[4] = {e4.x, e4.y, e4.z, e4.w};
        #pragma unroll
        for (int i = 0; i < 4; i++) {
            float xv = xb[(size_t)(d + i) * T_LEN];
            float df = ev[i] - xv;
            lsum = fmaf(df, df, lsum);
            ob[(size_t)(d + i) * T_LEN] = ev[i];
        }
    }
    #pragma unroll
    for (int o = 16; o; o >>= 1) lsum += __shfl_xor_sync(0xFFFFFFFFu, lsum, o);
    __shared__ float wsum[16];
    if ((tid & 31) == 0) wsum[wid] = lsum;
    __syncthreads();
    if (tid == 0) {
        float t = 0.f;
        #pragma unroll
        for (int i = 0; i < 16; i++) t += wsum[i];
        if (out_size > (long long)QN)
            atomicAdd(out + QN, t * (1.25f / 16777216.0f));
    }
}

// ---------------------------------------------------------------------------
extern "C" void kernel_launch(void* const* d_in, const int* in_sizes, int n_in,
                              void* d_out, int out_size) {
    const float* x   = (const float*)d_in[0];
    const float* emb = (const float*)d_in[1];
    if (n_in >= 2 && in_sizes[0] == K_CODES * DIM && in_sizes[1] == (int)QN) {
        const float* t = x; x = emb; emb = t;
    }
    float* out = (float*)d_out;

    const int smemA = 256 * 65 * 4;                  // 66560
    const int smemM = 3 * TILE;                      // 202752
    cudaFuncSetAttribute(vq_prepA, cudaFuncAttributeMaxDynamicSharedMemorySize, smemA);
    cudaFuncSetAttribute(vq_main_kernel, cudaFuncAttributeMaxDynamicSharedMemorySize, smemM);

    vq_prepB<<<K_CODES, 256>>>(emb, out, (long long)out_size);
    vq_prepA<<<B_SZ * 64, 256, smemA>>>(x);
    vq_main_kernel<<<N_ROWS / 128, NTHR, smemM>>>(x, emb, out, (long long)out_size);
}

// round 12
// speedup vs baseline: 4.1473x; 1.0199x over previous
#include <cuda_runtime.h>
#include <cuda_bf16.h>
#include <cstdint>
#include <cfloat>

#define K_CODES 1024
#define DIM     256
#define T_LEN   4096
#define B_SZ    16
#define N_ROWS  65536
#define QN      ((size_t)16777216)
#define RS      528                     // smem row stride (512B data + 16B pad)
#define TM      64                      // rows per CTA
#define NCODE   64                      // codes per B chunk
#define NCH     (K_CODES / NCODE)       // 16 chunks
#define A_BYTES (TM * RS)               // 33792
#define B_BYTES (NCODE * RS)            // 33792
#define NTHR    256

__device__ __align__(256) __nv_bfloat16 g_A[(size_t)N_ROWS * DIM];    // 32 MB
__device__ __align__(256) __nv_bfloat16 g_Bm[(size_t)K_CODES * DIM];  // 512 KB
__device__ __align__(256) float g_enT[DIM * K_CODES];
__device__ float g_norm[N_ROWS];

__device__ __forceinline__ void cp16(uint32_t dst, const void* src) {
    asm volatile("cp.async.cg.shared.global [%0], [%1], 16;\n" :: "r"(dst), "l"(src));
}
__device__ __forceinline__ void cp_commit() { asm volatile("cp.async.commit_group;\n"); }
template <int N> __device__ __forceinline__ void cp_waitg() {
    asm volatile("cp.async.wait_group %0;\n" :: "n"(N));
}
__device__ __forceinline__ void ldsm4(uint32_t* r, uint32_t a) {
    asm volatile("ldmatrix.sync.aligned.m8n8.x4.shared.b16 {%0,%1,%2,%3}, [%4];"
                 : "=r"(r[0]), "=r"(r[1]), "=r"(r[2]), "=r"(r[3]) : "r"(a));
}
__device__ __forceinline__ void ldsm2(uint32_t* r, uint32_t a) {
    asm volatile("ldmatrix.sync.aligned.m8n8.x2.shared.b16 {%0,%1}, [%2];"
                 : "=r"(r[0]), "=r"(r[1]) : "r"(a));
}
__device__ __forceinline__ void mma16816(float* c, const uint32_t* a, const uint32_t* b) {
    asm volatile(
        "mma.sync.aligned.m16n8k16.row.col.f32.bf16.bf16.f32 "
        "{%0,%1,%2,%3},{%4,%5,%6,%7},{%8,%9},{%0,%1,%2,%3};"
        : "+f"(c[0]), "+f"(c[1]), "+f"(c[2]), "+f"(c[3])
        : "r"(a[0]), "r"(a[1]), "r"(a[2]), "r"(a[3]), "r"(b[0]), "r"(b[1]));
}

// --------- prep B: normalize embeddings -> g_enT (fp32) + g_Bm (bf16) ------
__global__ void vq_prepB(const float* __restrict__ emb,
                         float* __restrict__ out, long long out_size) {
    int k = blockIdx.x, d = threadIdx.x;
    float v = emb[(size_t)k * DIM + d];
    float s = v * v;
    #pragma unroll
    for (int o = 16; o; o >>= 1) s += __shfl_xor_sync(0xFFFFFFFFu, s, o);
    __shared__ float ws[8]; __shared__ float rs_sh;
    if ((d & 31) == 0) ws[d >> 5] = s;
    __syncthreads();
    if (d == 0) {
        float t = 0.f;
        #pragma unroll
        for (int i = 0; i < 8; i++) t += ws[i];
        rs_sh = 1.0f / fmaxf(sqrtf(t), 1e-12f);
        if (k == 0 && out_size > (long long)QN) out[QN] = 0.0f;
    }
    __syncthreads();
    float en = v * rs_sh;
    g_enT[(size_t)d * K_CODES + k] = en;
    g_Bm[(size_t)k * DIM + d] = __float2bfloat16(en);
}

// --------- prep A: transpose x -> g_A [n][d] bf16, norms --------------------
__global__ void vq_prepA(const float* __restrict__ x) {
    extern __shared__ float xs[];                 // [256][65]
    const int tid = threadIdx.x;
    const int b  = blockIdx.x >> 6;
    const int t0 = (blockIdx.x & 63) << 6;
    #pragma unroll
    for (int i = 0; i < 64; i++) {
        int lin = i * 256 + tid;
        int d = lin >> 6, tt = lin & 63;
        xs[d * 65 + tt] = x[((size_t)b * DIM + d) * T_LEN + t0 + tt];
    }
    __syncthreads();
    const int q = tid & 3, tt = tid >> 2;
    const int n = b * T_LEN + t0 + tt;
    __nv_bfloat16 hib[64];
    float ss = 0.f;
    #pragma unroll
    for (int dd = 0; dd < 64; dd++) {
        float v = xs[(q * 64 + dd) * 65 + tt];
        ss = fmaf(v, v, ss);
        hib[dd] = __float2bfloat16(v);
    }
    uint4* h4 = (uint4*)hib;
    uint4* d0 = (uint4*)(g_A + (size_t)n * DIM + q * 64);
    #pragma unroll
    for (int i = 0; i < 8; i++) d0[i] = h4[i];
    ss += __shfl_xor_sync(0xFFFFFFFFu, ss, 1);
    ss += __shfl_xor_sync(0xFFFFFFFFu, ss, 2);
    if (q == 0) g_norm[n] = sqrtf(ss);
}

// --------- main: M=64 tiles, 2 CTAs/SM, bf16 mma.sync + argmax + rescue -----
__global__ void __launch_bounds__(NTHR, 2) vq_main_kernel(
    const float* __restrict__ x, const float* __restrict__ emb,
    float* __restrict__ out, long long out_size)
{
    extern __shared__ char smem[];
    const uint32_t sb = (uint32_t)__cvta_generic_to_shared(smem);
    const uint32_t sbB = sb + A_BYTES;            // two B stages follow A
    const int tid  = threadIdx.x;
    const int lane = tid & 31;
    const int wid  = tid >> 5;
    const int wm   = wid & 1;            // 32-row group
    const int wn   = wid >> 1;           // 16-code group (0..3)
    const int n0 = blockIdx.x * TM;
    const int b  = n0 >> 12;
    const int tl = n0 & 4095;

    // A tile: 64 rows x 256 bf16 -> its own cp.async group
    {
        const __nv_bfloat16* Asrc = g_A + (size_t)n0 * DIM;
        #pragma unroll
        for (int i = 0; i < 8; i++) {
            int lin = i * NTHR + tid;            // 0..2047
            int row = lin >> 5, q = lin & 31;
            cp16(sb + (uint32_t)(row * RS + q * 16), Asrc + (size_t)row * DIM + q * 8);
        }
        cp_commit();
    }
    auto loadB = [&](int nc) {
        const __nv_bfloat16* Bsrc = g_Bm + (size_t)(nc * NCODE) * DIM;
        uint32_t stg = sbB + (uint32_t)(nc & 1) * B_BYTES;
        #pragma unroll
        for (int i = 0; i < 8; i++) {
            int lin = i * NTHR + tid;
            int row = lin >> 5, q = lin & 31;
            cp16(stg + (uint32_t)(row * RS + q * 16), Bsrc + (size_t)row * DIM + q * 8);
        }
        cp_commit();
    };
    loadB(0); loadB(1);

    float rm1[4], rm2[4];
    int   ri1[4];
    #pragma unroll
    for (int i = 0; i < 4; i++) { rm1[i] = -FLT_MAX; rm2[i] = -FLT_MAX; ri1[i] = 0; }

    #pragma unroll 1
    for (int nc = 0; nc < NCH; nc++) {
        if (nc < NCH - 2) cp_waitg<1>(); else cp_waitg<0>();
        __syncthreads();                          // A + B-chunk nc resident

        float acc[2][2][4];
        #pragma unroll
        for (int mt = 0; mt < 2; mt++)
            #pragma unroll
            for (int nt = 0; nt < 2; nt++)
                #pragma unroll
                for (int c = 0; c < 4; c++) acc[mt][nt][c] = 0.f;

        const uint32_t stgB = sbB + (uint32_t)(nc & 1) * B_BYTES;
        #pragma unroll 4
        for (int ks = 0; ks < 16; ks++) {
            uint32_t af[2][4], bf[2][2];
            #pragma unroll
            for (int mt = 0; mt < 2; mt++) {
                int row = wm * 32 + mt * 16 + (lane & 15);
                ldsm4(af[mt], sb + (uint32_t)(row * RS + ks * 32 + (lane >> 4) * 16));
            }
            #pragma unroll
            for (int nt = 0; nt < 2; nt++) {
                int rb = wn * 16 + nt * 8 + (lane & 7);
                ldsm2(bf[nt], stgB + (uint32_t)(rb * RS + ks * 32 + ((lane >> 3) & 1) * 16));
            }
            #pragma unroll
            for (int mt = 0; mt < 2; mt++)
                #pragma unroll
                for (int nt = 0; nt < 2; nt++)
                    mma16816(acc[mt][nt], af[mt], bf[nt]);
        }

        // fold this 64-code chunk into running top-2
        {
            int cb = nc * NCODE + wn * 16 + 2 * (lane & 3);
            #pragma unroll
            for (int mt = 0; mt < 2; mt++)
                #pragma unroll
                for (int nt = 0; nt < 2; nt++) {
                    int col = cb + nt * 8;
                    #pragma unroll
                    for (int c = 0; c < 4; c++) {
                        int slot = mt * 2 + (c >> 1);
                        int ci = col + (c & 1);
                        float v = acc[mt][nt][c];
                        if (v > rm1[slot]) { rm2[slot] = rm1[slot]; rm1[slot] = v; ri1[slot] = ci; }
                        else if (v > rm2[slot]) rm2[slot] = v;
                    }
                }
        }
        __syncthreads();                          // stage nc&1 free
        if (nc + 2 < NCH) loadB(nc + 2);
    }
    __syncthreads();

    // ---- cross-partition top-2 reduce (reuse A region as scratch) ----
    float* redm1 = (float*)smem;                 // [64][16] = 4KB
    int*   redix = (int*)(smem + 4096);          // [64][16]
    float* redm2 = (float*)(smem + 8192);        // [64][16]
    const int p = wn * 4 + (lane & 3);
    #pragma unroll
    for (int slot = 0; slot < 4; slot++) {
        int row = wm * 32 + (slot >> 1) * 16 + (slot & 1) * 8 + (lane >> 2);
        redm1[row * 16 + p] = rm1[slot];
        redix[row * 16 + p] = ri1[slot];
        redm2[row * 16 + p] = rm2[slot];
    }
    __syncthreads();

    int*   idx_s = (int*)(smem + 12288);         // [64]
    int*   rlist = idx_s + 64;                   // [64]
    int*   rcnt  = idx_s + 128;
    float* xs4   = (float*)(smem + 13312);       // [4][256] = 4KB
    float* rwv   = (float*)(smem + 17408);       // [4][8]
    int*   rwi   = (int*)(smem + 17536);         // [4][8]

    if (tid == 0) *rcnt = 0;
    __syncthreads();
    if (tid < TM) {
        float g1 = -FLT_MAX, g2 = -FLT_MAX; int gi = 0;
        #pragma unroll 1
        for (int j = 0; j < 16; j++) {
            float m1 = redm1[tid * 16 + j];
            float m2 = redm2[tid * 16 + j];
            int   ix = redix[tid * 16 + j];
            if (m1 > g1) { g2 = fmaxf(fmaxf(g1, m2), g2); g1 = m1; gi = ix; }
            else         { g2 = fmaxf(g2, m1); }
        }
        idx_s[tid] = gi;
        if (g1 - g2 < 1e-3f * g_norm[n0 + tid]) {   // ~7 sigma of bf16 dot-diff error
            int q = atomicAdd(rcnt, 1); rlist[q] = tid;
        }
    }
    __syncthreads();

    // ---- batched exact fp32 rescue: 4 rows per g_enT sweep, 4 codes/thread --
    const int nr = *rcnt;
    #pragma unroll 1
    for (int e0 = 0; e0 < nr; e0 += 4) {
        const int nb = min(4, nr - e0);
        #pragma unroll
        for (int i = 0; i < 4; i++) {
            int lin = i * NTHR + tid;            // 0..1023
            int r = lin >> 8, d = lin & 255;
            int rr = rlist[e0 + (r < nb ? r : 0)];
            xs4[r * 256 + d] = x[((size_t)b * DIM + d) * T_LEN + ((n0 + rr) & 4095)];
        }
        __syncthreads();
        float a0[4], a1[4], a2[4], a3[4];
        #pragma unroll
        for (int r = 0; r < 4; r++) { a0[r] = 0.f; a1[r] = 0.f; a2[r] = 0.f; a3[r] = 0.f; }
        #pragma unroll 4
        for (int d = 0; d < 256; d++) {
            const float* ed = g_enT + d * K_CODES + tid;
            float e0v = ed[0], e1v = ed[256], e2v = ed[512], e3v = ed[768];
            #pragma unroll
            for (int r = 0; r < 4; r++) {
                float xv = xs4[r * 256 + d];
                a0[r] = fmaf(xv, e0v, a0[r]);
                a1[r] = fmaf(xv, e1v, a1[r]);
                a2[r] = fmaf(xv, e2v, a2[r]);
                a3[r] = fmaf(xv, e3v, a3[r]);
            }
        }
        #pragma unroll 1
        for (int r = 0; r < nb; r++) {
            float bv = a0[r]; int bi = tid;
            if (a1[r] > bv) { bv = a1[r]; bi = tid + 256; }
            if (a2[r] > bv) { bv = a2[r]; bi = tid + 512; }
            if (a3[r] > bv) { bv = a3[r]; bi = tid + 768; }
            #pragma unroll
            for (int o = 16; o; o >>= 1) {
                float ov = __shfl_xor_sync(0xFFFFFFFFu, bv, o);
                int   oi = __shfl_xor_sync(0xFFFFFFFFu, bi, o);
                if (ov > bv || (ov == bv && oi < bi)) { bv = ov; bi = oi; }
            }
            if (lane == 0) { rwv[r * 8 + wid] = bv; rwi[r * 8 + wid] = bi; }
        }
        __syncthreads();
        if (tid < nb) {
            float best = rwv[tid * 8]; int besti = rwi[tid * 8];
            #pragma unroll
            for (int j = 1; j < 8; j++) {
                float v = rwv[tid * 8 + j]; int ix = rwi[tid * 8 + j];
                if (v > best || (v == best && ix < besti)) { best = v; besti = ix; }
            }
            idx_s[rlist[e0 + tid]] = besti;
        }
        __syncthreads();
    }

    if (tid < TM && out_size >= (long long)(QN + 1 + N_ROWS))
        out[QN + 1 + n0 + tid] = (float)idx_s[tid];

    // ---- gather + quantized write + exact loss (256 threads: 64 dims each) --
    const int r  = tid & 63;
    const int dq = tid >> 6;
    const int myidx = idx_s[r];
    const float4* erow4 = (const float4*)(emb + (size_t)myidx * DIM + dq * 64);
    const float* xb = x + ((size_t)b * DIM + dq * 64) * T_LEN + tl + r;
    float* ob = out + ((size_t)b * DIM + dq * 64) * T_LEN + tl + r;
    float lsum = 0.f;
    #pragma unroll 4
    for (int dj = 0; dj < 16; ++dj) {
        float4 e4 = erow4[dj];
        int d = dj * 4;
        float ev[4] = {e4.x, e4.y, e4.z, e4.w};
        #pragma unroll
        for (int i = 0; i < 4; i++) {
            float xv = xb[(size_t)(d + i) * T_LEN];
            float df = ev[i] - xv;
            lsum = fmaf(df, df, lsum);
            ob[(size_t)(d + i) * T_LEN] = ev[i];
        }
    }
    #pragma unroll
    for (int o = 16; o; o >>= 1) lsum += __shfl_xor_sync(0xFFFFFFFFu, lsum, o);
    __shared__ float wsum[8];
    if ((tid & 31) == 0) wsum[wid] = lsum;
    __syncthreads();
    if (tid == 0) {
        float t = 0.f;
        #pragma unroll
        for (int i = 0; i < 8; i++) t += wsum[i];
        if (out_size > (long long)QN)
            atomicAdd(out + QN, t * (1.25f / 16777216.0f));
    }
}

// ---------------------------------------------------------------------------
extern "C" void kernel_launch(void* const* d_in, const int* in_sizes, int n_in,
                              void* d_out, int out_size) {
    const float* x   = (const float*)d_in[0];
    const float* emb = (const float*)d_in[1];
    if (n_in >= 2 && in_sizes[0] == K_CODES * DIM && in_sizes[1] == (int)QN) {
        const float* t = x; x = emb; emb = t;
    }
    float* out = (float*)d_out;

    const int smemA = 256 * 65 * 4;                      // 66560
    const int smemM = A_BYTES + 2 * B_BYTES;             // 101376 -> 2 CTAs/SM
    cudaFuncSetAttribute(vq_prepA, cudaFuncAttributeMaxDynamicSharedMemorySize, smemA);
    cudaFuncSetAttribute(vq_main_kernel, cudaFuncAttributeMaxDynamicSharedMemorySize, smemM);

    vq_prepB<<<K_CODES, 256>>>(emb, out, (long long)out_size);
    vq_prepA<<<B_SZ * 64, 256, smemA>>>(x);
    vq_main_kernel<<<N_ROWS / TM, NTHR, smemM>>>(x, emb, out, (long long)out_size);
}

// round 13
// speedup vs baseline: 5.9829x; 1.4426x over previous
#include <cuda_runtime.h>
#include <cuda_fp16.h>
#include <cstdint>
#include <cfloat>

#define K_CODES 1024
#define DIM     256
#define T_LEN   4096
#define B_SZ    16
#define N_ROWS  65536
#define QN      ((size_t)16777216)
#define RS      528                     // smem row stride (512B data + 16B pad)
#define TM      64                      // rows per CTA
#define NCODE   64                      // codes per B chunk
#define NCH     (K_CODES / NCODE)       // 16 chunks
#define A_BYTES (TM * RS)               // 33792
#define B_BYTES (NCODE * RS)            // 33792
#define XTRA    (A_BYTES + 2 * B_BYTES) // offset of norm scratch
#define SMEM_M  (XTRA + 2048)           // 103424 -> 2 CTAs/SM
#define NTHR    256
#define RTHR    256
#define RGRID   128

__device__ __align__(256) __half g_Bh[(size_t)K_CODES * DIM];   // fp16 normalized emb
__device__ __align__(256) float g_enT[DIM * K_CODES];           // fp32 normalized emb^T
__device__ float g_elen[K_CODES];
__device__ float g_e2[K_CODES];
__device__ int   g_rn;
__device__ int   g_rlist[N_ROWS];

__device__ __forceinline__ void cp16(uint32_t dst, const void* src) {
    asm volatile("cp.async.cg.shared.global [%0], [%1], 16;\n" :: "r"(dst), "l"(src));
}
__device__ __forceinline__ void cp_commit() { asm volatile("cp.async.commit_group;\n"); }
template <int N> __device__ __forceinline__ void cp_waitg() {
    asm volatile("cp.async.wait_group %0;\n" :: "n"(N));
}
__device__ __forceinline__ void ldsm4(uint32_t* r, uint32_t a) {
    asm volatile("ldmatrix.sync.aligned.m8n8.x4.shared.b16 {%0,%1,%2,%3}, [%4];"
                 : "=r"(r[0]), "=r"(r[1]), "=r"(r[2]), "=r"(r[3]) : "r"(a));
}
__device__ __forceinline__ void ldsm2(uint32_t* r, uint32_t a) {
    asm volatile("ldmatrix.sync.aligned.m8n8.x2.shared.b16 {%0,%1}, [%2];"
                 : "=r"(r[0]), "=r"(r[1]) : "r"(a));
}
__device__ __forceinline__ void mma16816(float* c, const uint32_t* a, const uint32_t* b) {
    asm volatile(
        "mma.sync.aligned.m16n8k16.row.col.f32.f16.f16.f32 "
        "{%0,%1,%2,%3},{%4,%5,%6,%7},{%8,%9},{%0,%1,%2,%3};"
        : "+f"(c[0]), "+f"(c[1]), "+f"(c[2]), "+f"(c[3])
        : "r"(a[0]), "r"(a[1]), "r"(a[2]), "r"(a[3]), "r"(b[0]), "r"(b[1]));
}

// --------- prep B: normalize emb -> g_enT + g_Bh, norms, zero counters -----
__global__ void vq_prepB(const float* __restrict__ emb,
                         float* __restrict__ out, long long out_size) {
    int k = blockIdx.x, d = threadIdx.x;
    float v = emb[(size_t)k * DIM + d];
    float s = v * v;
    #pragma unroll
    for (int o = 16; o; o >>= 1) s += __shfl_xor_sync(0xFFFFFFFFu, s, o);
    __shared__ float ws[8]; __shared__ float rs_sh;
    if ((d & 31) == 0) ws[d >> 5] = s;
    __syncthreads();
    if (d == 0) {
        float t = 0.f;
        #pragma unroll
        for (int i = 0; i < 8; i++) t += ws[i];
        float nrm = sqrtf(t);
        rs_sh = 1.0f / fmaxf(nrm, 1e-12f);
        g_elen[k] = nrm;
        g_e2[k] = t;
        if (k == 0) {
            g_rn = 0;
            if (out_size > (long long)QN) out[QN] = 0.0f;
        }
    }
    __syncthreads();
    float en = v * rs_sh;
    g_enT[(size_t)d * K_CODES + k] = en;
    g_Bh[(size_t)k * DIM + d] = __float2half_rn(en);
}

// --------- main: fused prologue + fp16 mma.sync GEMM + argmax + epilogue ----
__global__ void __launch_bounds__(NTHR, 2) vq_main_kernel(
    const float* __restrict__ x, const float* __restrict__ emb,
    float* __restrict__ out, long long out_size)
{
    extern __shared__ char smem[];
    const uint32_t sb = (uint32_t)__cvta_generic_to_shared(smem);
    const uint32_t sbB = sb + A_BYTES;
    const int tid  = threadIdx.x;
    const int lane = tid & 31;
    const int wid  = tid >> 5;
    const int wm   = wid & 1;
    const int wn   = wid >> 1;
    const int n0 = blockIdx.x * TM;
    const int b  = n0 >> 12;
    const int tl = n0 & 4095;

    float* xn4 = (float*)(smem + XTRA);          // [4][64]
    float* xn2 = (float*)(smem + XTRA + 1024);   // [64] (norm^2)

    auto loadB = [&](int nc) {
        const __half* Bsrc = g_Bh + (size_t)(nc * NCODE) * DIM;
        uint32_t stg = sbB + (uint32_t)(nc & 1) * B_BYTES;
        #pragma unroll
        for (int i = 0; i < 8; i++) {
            int lin = i * NTHR + tid;
            int row = lin >> 5, q = lin & 31;
            cp16(stg + (uint32_t)(row * RS + q * 16), Bsrc + (size_t)row * DIM + q * 8);
        }
        cp_commit();
    };
    loadB(0); loadB(1);

    // ---- fused prep A: load x tile, fp16 convert into smem, row norms ----
    {
        const int r = tid & 63;
        float ss = 0.f;
        #pragma unroll 8
        for (int i = 0; i < 64; i++) {
            int d = i * 4 + (tid >> 6);
            float v = x[((size_t)b * DIM + d) * T_LEN + tl + r];
            ss = fmaf(v, v, ss);
            *(__half*)(smem + r * RS + d * 2) = __float2half_rn(v);
        }
        xn4[(tid >> 6) * 64 + r] = ss;
    }
    __syncthreads();
    if (tid < TM)
        xn2[tid] = xn4[tid] + xn4[64 + tid] + xn4[128 + tid] + xn4[192 + tid];

    float rm1[4], rm2[4];
    int   ri1[4];
    #pragma unroll
    for (int i = 0; i < 4; i++) { rm1[i] = -FLT_MAX; rm2[i] = -FLT_MAX; ri1[i] = 0; }

    #pragma unroll 1
    for (int nc = 0; nc < NCH; nc++) {
        if (nc < NCH - 2) cp_waitg<1>(); else cp_waitg<0>();
        __syncthreads();                          // A(STS) + B-chunk nc resident

        float acc[2][2][4];
        #pragma unroll
        for (int mt = 0; mt < 2; mt++)
            #pragma unroll
            for (int nt = 0; nt < 2; nt++)
                #pragma unroll
                for (int c = 0; c < 4; c++) acc[mt][nt][c] = 0.f;

        const uint32_t stgB = sbB + (uint32_t)(nc & 1) * B_BYTES;
        #pragma unroll 4
        for (int ks = 0; ks < 16; ks++) {
            uint32_t af[2][4], bf[2][2];
            #pragma unroll
            for (int mt = 0; mt < 2; mt++) {
                int row = wm * 32 + mt * 16 + (lane & 15);
                ldsm4(af[mt], sb + (uint32_t)(row * RS + ks * 32 + (lane >> 4) * 16));
            }
            #pragma unroll
            for (int nt = 0; nt < 2; nt++) {
                int rb = wn * 16 + nt * 8 + (lane & 7);
                ldsm2(bf[nt], stgB + (uint32_t)(rb * RS + ks * 32 + ((lane >> 3) & 1) * 16));
            }
            #pragma unroll
            for (int mt = 0; mt < 2; mt++)
                #pragma unroll
                for (int nt = 0; nt < 2; nt++)
                    mma16816(acc[mt][nt], af[mt], bf[nt]);
        }

        {
            int cb = nc * NCODE + wn * 16 + 2 * (lane & 3);
            #pragma unroll
            for (int mt = 0; mt < 2; mt++)
                #pragma unroll
                for (int nt = 0; nt < 2; nt++) {
                    int col = cb + nt * 8;
                    #pragma unroll
                    for (int c = 0; c < 4; c++) {
                        int slot = mt * 2 + (c >> 1);
                        int ci = col + (c & 1);
                        float v = acc[mt][nt][c];
                        if (v > rm1[slot]) { rm2[slot] = rm1[slot]; rm1[slot] = v; ri1[slot] = ci; }
                        else if (v > rm2[slot]) rm2[slot] = v;
                    }
                }
        }
        __syncthreads();
        if (nc + 2 < NCH) loadB(nc + 2);
    }
    __syncthreads();

    // ---- cross-partition top-2 reduce (reuse A region as scratch) ----
    float* redm1 = (float*)smem;                 // [64][16]
    int*   redix = (int*)(smem + 4096);          // [64][16]
    float* redm2 = (float*)(smem + 8192);        // [64][16]
    const int p = wn * 4 + (lane & 3);
    #pragma unroll
    for (int slot = 0; slot < 4; slot++) {
        int row = wm * 32 + (slot >> 1) * 16 + (slot & 1) * 8 + (lane >> 2);
        redm1[row * 16 + p] = rm1[slot];
        redix[row * 16 + p] = ri1[slot];
        redm2[row * 16 + p] = rm2[slot];
    }
    __syncthreads();

    int*   idx_s = (int*)(smem + 12288);         // [64]
    float* bestv = (float*)(smem + 12544);       // [64]
    int*   flg   = (int*)(smem + 12800);         // [64]

    if (tid < TM) {
        float g1 = -FLT_MAX, g2 = -FLT_MAX; int gi = 0;
        #pragma unroll 1
        for (int j = 0; j < 16; j++) {
            float m1 = redm1[tid * 16 + j];
            float m2 = redm2[tid * 16 + j];
            int   ix = redix[tid * 16 + j];
            if (m1 > g1) { g2 = fmaxf(fmaxf(g1, m2), g2); g1 = m1; gi = ix; }
            else         { g2 = fmaxf(g2, m1); }
        }
        idx_s[tid] = gi;
        bestv[tid] = g1;
        int f = (g1 - g2 < 2e-4f * sqrtf(xn2[tid])) ? 1 : 0;  // fp16-dot 10+ sigma
        flg[tid] = f;
        if (f) {
            int q = atomicAdd(&g_rn, 1);
            g_rlist[q] = n0 + tid;
        }
    }
    __syncthreads();

    if (tid < TM && !flg[tid] && out_size >= (long long)(QN + 1 + N_ROWS))
        out[QN + 1 + n0 + tid] = (float)idx_s[tid];

    // ---- loss from norms (per-row, non-flagged) ----
    if (tid < TM) {
        float lr = 0.f;
        if (!flg[tid]) {
            int gi = idx_s[tid];
            lr = xn2[tid] - 2.0f * g_elen[gi] * bestv[tid] + g_e2[gi];
        }
        redm1[tid] = lr;
    }
    __syncthreads();
    if (tid == 0 && out_size > (long long)QN) {
        float t = 0.f;
        #pragma unroll 1
        for (int j = 0; j < TM; j++) t += redm1[j];
        atomicAdd(out + QN, t * (1.25f / 16777216.0f));
    }

    // ---- gather + quantized write (non-flagged rows) ----
    const int r  = tid & 63;
    const int dq = tid >> 6;
    if (!flg[r]) {
        const int myidx = idx_s[r];
        const float4* erow4 = (const float4*)(emb + (size_t)myidx * DIM + dq * 64);
        float* ob = out + ((size_t)b * DIM + dq * 64) * T_LEN + tl + r;
        #pragma unroll 4
        for (int dj = 0; dj < 16; ++dj) {
            float4 e4 = erow4[dj];
            int d = dj * 4;
            ob[(size_t)(d + 0) * T_LEN] = e4.x;
            ob[(size_t)(d + 1) * T_LEN] = e4.y;
            ob[(size_t)(d + 2) * T_LEN] = e4.z;
            ob[(size_t)(d + 3) * T_LEN] = e4.w;
        }
    }
}

// --------- rescue: exact fp32 argmax + outputs for flagged rows -------------
__global__ void __launch_bounds__(RTHR, 2) vq_rescue(
    const float* __restrict__ x, const float* __restrict__ emb,
    float* __restrict__ out, long long out_size)
{
    __shared__ float xs8[8 * 256];
    __shared__ float xn8[8];
    __shared__ float rwv[8 * 8];
    __shared__ int   rwi[8 * 8];
    __shared__ int   bsel[8];
    const int tid = threadIdx.x, lane = tid & 31, wid = tid >> 5;
    const int total = g_rn;

    #pragma unroll 1
    for (int base = blockIdx.x * 8; base < total; base += gridDim.x * 8) {
        const int nb = min(8, total - base);
        #pragma unroll
        for (int i = 0; i < 8; i++) {
            int lin = i * RTHR + tid;
            int r = lin >> 8, d = lin & 255;
            int nn = g_rlist[base + (r < nb ? r : 0)];
            xs8[r * 256 + d] = x[((size_t)(nn >> 12) * DIM + d) * T_LEN + (nn & 4095)];
        }
        __syncthreads();
        {   // row norms: warp wid handles row wid
            float s = 0.f;
            #pragma unroll
            for (int j = 0; j < 8; j++) {
                float v = xs8[wid * 256 + lane + 32 * j];
                s = fmaf(v, v, s);
            }
            #pragma unroll
            for (int o = 16; o; o >>= 1) s += __shfl_xor_sync(0xFFFFFFFFu, s, o);
            if (lane == 0) xn8[wid] = s;
        }
        float a0[8], a1[8], a2[8], a3[8];
        #pragma unroll
        for (int r = 0; r < 8; r++) { a0[r] = 0.f; a1[r] = 0.f; a2[r] = 0.f; a3[r] = 0.f; }
        #pragma unroll 4
        for (int d = 0; d < 256; d++) {
            const float* ed = g_enT + d * K_CODES + tid;
            float e0 = ed[0], e1 = ed[256], e2v = ed[512], e3 = ed[768];
            #pragma unroll
            for (int r = 0; r < 8; r++) {
                float xv = xs8[r * 256 + d];
                a0[r] = fmaf(xv, e0, a0[r]);
                a1[r] = fmaf(xv, e1, a1[r]);
                a2[r] = fmaf(xv, e2v, a2[r]);
                a3[r] = fmaf(xv, e3, a3[r]);
            }
        }
        #pragma unroll 1
        for (int r = 0; r < nb; r++) {
            float bv = a0[r]; int bi = tid;
            if (a1[r] > bv) { bv = a1[r]; bi = tid + 256; }
            if (a2[r] > bv) { bv = a2[r]; bi = tid + 512; }
            if (a3[r] > bv) { bv = a3[r]; bi = tid + 768; }
            #pragma unroll
            for (int o = 16; o; o >>= 1) {
                float ov = __shfl_xor_sync(0xFFFFFFFFu, bv, o);
                int   oi = __shfl_xor_sync(0xFFFFFFFFu, bi, o);
                if (ov > bv || (ov == bv && oi < bi)) { bv = ov; bi = oi; }
            }
            if (lane == 0) { rwv[r * 8 + wid] = bv; rwi[r * 8 + wid] = bi; }
        }
        __syncthreads();
        if (tid < nb) {
            float best = rwv[tid * 8]; int besti = rwi[tid * 8];
            #pragma unroll
            for (int j = 1; j < 8; j++) {
                float v = rwv[tid * 8 + j]; int ix = rwi[tid * 8 + j];
                if (v > best || (v == best && ix < besti)) { best = v; besti = ix; }
            }
            bsel[tid] = besti;
            int nn = g_rlist[base + tid];
            if (out_size >= (long long)(QN + 1 + N_ROWS))
                out[QN + 1 + nn] = (float)besti;
            if (out_size > (long long)QN)
                atomicAdd(out + QN,
                    (xn8[tid] - 2.0f * g_elen[besti] * best + g_e2[besti]) * (1.25f / 16777216.0f));
        }
        __syncthreads();
        #pragma unroll 1
        for (int r = 0; r < nb; r++) {
            int nn = g_rlist[base + r];
            int bi = bsel[r];
            out[((size_t)(nn >> 12) * DIM + tid) * T_LEN + (nn & 4095)] =
                emb[(size_t)bi * DIM + tid];
        }
        __syncthreads();
    }
}

// ---------------------------------------------------------------------------
extern "C" void kernel_launch(void* const* d_in, const int* in_sizes, int n_in,
                              void* d_out, int out_size) {
    const float* x   = (const float*)d_in[0];
    const float* emb = (const float*)d_in[1];
    if (n_in >= 2 && in_sizes[0] == K_CODES * DIM && in_sizes[1] == (int)QN) {
        const float* t = x; x = emb; emb = t;
    }
    float* out = (float*)d_out;

    cudaFuncSetAttribute(vq_main_kernel, cudaFuncAttributeMaxDynamicSharedMemorySize, SMEM_M);

    vq_prepB<<<K_CODES, 256>>>(emb, out, (long long)out_size);
    vq_main_kernel<<<N_ROWS / TM, NTHR, SMEM_M>>>(x, emb, out, (long long)out_size);
    vq_rescue<<<RGRID, RTHR>>>(x, emb, out, (long long)out_size);
}